// round 1
// baseline (speedup 1.0000x reference)
#include <cuda_runtime.h>

// ROI-align-style pooling (RoiPoolingConv): img (1,128,128,1024) NHWC fp32,
// rois (1,256,4) [x,y,w,h] in pixels, out (1,256,7,7,1024) fp32.
//
// One block per (roi, iy, ix) bin. 256 threads x float4 = 1024 channels.
// Memory-bound gather: 4 coalesced 4KB corner reads + 4KB write per block.

#define POOL  7
#define NROIS 256
#define HH    128
#define WW    128
#define CC    1024

__global__ __launch_bounds__(256, 8)
void roi_pool_kernel(const float* __restrict__ img,
                     const float* __restrict__ rois,
                     float* __restrict__ out)
{
    const int bin = blockIdx.x;           // 0 .. 256*49-1
    const int roi = bin / (POOL * POOL);
    const int b49 = bin - roi * (POOL * POOL);
    const int iy  = b49 / POOL;
    const int ix  = b49 - iy * POOL;

    // roi = [x, y, w, h]; c = (int)(roi * 1/16)  (truncation, same as astype)
    const float4 r = reinterpret_cast<const float4*>(rois)[roi];
    const int x0 = (int)(r.x * 0.0625f);
    const int y0 = (int)(r.y * 0.0625f);
    const int w  = (int)(r.z * 0.0625f);
    const int h  = (int)(r.w * 0.0625f);

    // sample coords: s = i * (dim / POOL)
    const float sy = (float)iy * ((float)h / (float)POOL);
    const float sx = (float)ix * ((float)w / (float)POOL);
    const float fy = floorf(sy);
    const float fx = floorf(sx);
    const float ty = sy - fy;
    const float tx = sx - fx;

    const int y_lo = (int)fy;
    const int x_lo = (int)fx;
    const int y_hi = min(y_lo + 1, max(h - 1, 0));
    const int x_hi = min(x_lo + 1, max(w - 1, 0));

    const int gy0 = min(max(y0 + y_lo, 0), HH - 1);
    const int gy1 = min(max(y0 + y_hi, 0), HH - 1);
    const int gx0 = min(max(x0 + x_lo, 0), WW - 1);
    const int gx1 = min(max(x0 + x_hi, 0), WW - 1);

    const float4* __restrict__ p00 =
        reinterpret_cast<const float4*>(img + (size_t)(gy0 * WW + gx0) * CC);
    const float4* __restrict__ p01 =
        reinterpret_cast<const float4*>(img + (size_t)(gy0 * WW + gx1) * CC);
    const float4* __restrict__ p10 =
        reinterpret_cast<const float4*>(img + (size_t)(gy1 * WW + gx0) * CC);
    const float4* __restrict__ p11 =
        reinterpret_cast<const float4*>(img + (size_t)(gy1 * WW + gx1) * CC);

    float4* __restrict__ po =
        reinterpret_cast<float4*>(out + (size_t)bin * CC);

    const int t = threadIdx.x;            // 0..255, 256 float4 = 1024 floats

    const float4 a = p00[t];
    const float4 b = p01[t];
    const float4 c = p10[t];
    const float4 d = p11[t];

    float4 o;
    {
        float top, bot;
        top = a.x + tx * (b.x - a.x);
        bot = c.x + tx * (d.x - c.x);
        o.x = top + ty * (bot - top);
        top = a.y + tx * (b.y - a.y);
        bot = c.y + tx * (d.y - c.y);
        o.y = top + ty * (bot - top);
        top = a.z + tx * (b.z - a.z);
        bot = c.z + tx * (d.z - c.z);
        o.z = top + ty * (bot - top);
        top = a.w + tx * (b.w - a.w);
        bot = c.w + tx * (d.w - c.w);
        o.w = top + ty * (bot - top);
    }
    po[t] = o;
}

extern "C" void kernel_launch(void* const* d_in, const int* in_sizes, int n_in,
                              void* d_out, int out_size)
{
    // metadata order: img (1*128*128*1024), rois (1*256*4). Guard by size.
    const float* img  = (const float*)d_in[0];
    const float* rois = (const float*)d_in[1];
    if (n_in >= 2 && in_sizes[0] < in_sizes[1]) {
        img  = (const float*)d_in[1];
        rois = (const float*)d_in[0];
    }
    float* out = (float*)d_out;

    const int nblocks = NROIS * POOL * POOL;   // 12544
    roi_pool_kernel<<<nblocks, 256>>>(img, rois, out);
}